// round 1
// baseline (speedup 1.0000x reference)
#include <cuda_runtime.h>
#include <math.h>

#define HID     512
#define EMB     512
#define VOCAB   31
#define T_ENC   16384
#define MAX_LEN 100
#define EOS_IDX 29

#define NB_B 128   // score blocks
#define NB_C 128   // summary blocks

// ---------------- device scratch (static globals; no allocation) -------------
__device__ float g_h[HID];
__device__ float g_y[EMB];
__device__ float g_hnew[HID];
__device__ float g_scores[T_ENC];
__device__ float g_blockmax[NB_B];
__device__ float g_partU[NB_C * HID];
__device__ float g_partZ[NB_C];
__device__ float g_Z[MAX_LEN];
__device__ int   g_best[MAX_LEN];

// ---------------- init: h=0, y=embed[EOS] ------------------------------------
__global__ void k_init(const float* __restrict__ embed) {
    int i = threadIdx.x;               // 512 threads
    g_h[i] = 0.f;
    g_y[i] = embed[EOS_IDX * EMB + i];
}

// ---------------- GRU cell: 64 blocks x 256 threads (512 warps) --------------
__global__ void k_gru(const float* __restrict__ w_ih, const float* __restrict__ w_hh,
                      const float* __restrict__ b_ih, const float* __restrict__ b_hh) {
    __shared__ __align__(16) float4 sx[EMB / 4];
    __shared__ __align__(16) float4 sh[HID / 4];
    int tid = threadIdx.x;
    if (tid < 128)       sx[tid]       = ((const float4*)g_y)[tid];
    else if (tid < 256)  sh[tid - 128] = ((const float4*)g_h)[tid - 128];
    __syncthreads();

    int wid = tid >> 5, lane = tid & 31;
    int j = blockIdx.x * 8 + wid;      // output index 0..511

    const float4* wr = (const float4*)(w_ih + (size_t)j * 512);
    const float4* wz = (const float4*)(w_ih + (size_t)(512 + j) * 512);
    const float4* wn = (const float4*)(w_ih + (size_t)(1024 + j) * 512);
    const float4* vr = (const float4*)(w_hh + (size_t)j * 512);
    const float4* vz = (const float4*)(w_hh + (size_t)(512 + j) * 512);
    const float4* vn = (const float4*)(w_hh + (size_t)(1024 + j) * 512);

    float gxr = 0.f, gxz = 0.f, gxn = 0.f, ghr = 0.f, ghz = 0.f, ghn = 0.f;
#pragma unroll
    for (int i = 0; i < 4; i++) {
        int k = lane + 32 * i;
        float4 x4 = sx[k], h4 = sh[k], a;
        a = wr[k]; gxr += a.x * x4.x + a.y * x4.y + a.z * x4.z + a.w * x4.w;
        a = wz[k]; gxz += a.x * x4.x + a.y * x4.y + a.z * x4.z + a.w * x4.w;
        a = wn[k]; gxn += a.x * x4.x + a.y * x4.y + a.z * x4.z + a.w * x4.w;
        a = vr[k]; ghr += a.x * h4.x + a.y * h4.y + a.z * h4.z + a.w * h4.w;
        a = vz[k]; ghz += a.x * h4.x + a.y * h4.y + a.z * h4.z + a.w * h4.w;
        a = vn[k]; ghn += a.x * h4.x + a.y * h4.y + a.z * h4.z + a.w * h4.w;
    }
#pragma unroll
    for (int o = 16; o > 0; o >>= 1) {
        gxr += __shfl_xor_sync(~0u, gxr, o);
        gxz += __shfl_xor_sync(~0u, gxz, o);
        gxn += __shfl_xor_sync(~0u, gxn, o);
        ghr += __shfl_xor_sync(~0u, ghr, o);
        ghz += __shfl_xor_sync(~0u, ghz, o);
        ghn += __shfl_xor_sync(~0u, ghn, o);
    }
    if (lane == 0) {
        float ar = (gxr + b_ih[j])        + (ghr + b_hh[j]);
        float az = (gxz + b_ih[512 + j])  + (ghz + b_hh[512 + j]);
        float xn =  gxn + b_ih[1024 + j];
        float hn =  ghn + b_hh[1024 + j];
        float r = 1.f / (1.f + expf(-ar));
        float z = 1.f / (1.f + expf(-az));
        float n = tanhf(xn + r * hn);
        g_hnew[j] = (1.f - z) * n + z * g_h[j];
    }
}

// ---------------- scores + per-block max: 128 blocks x 256 threads -----------
__global__ void k_scores(const float* __restrict__ enc) {
    __shared__ __align__(16) float4 sh4[128];
    __shared__ float smax[8];
    int tid = threadIdx.x;
    if (tid < 128) sh4[tid] = ((const float4*)g_hnew)[tid];
    __syncthreads();

    int wid = tid >> 5, lane = tid & 31;
    int wg = blockIdx.x * 8 + wid;           // 0..1023
    const float scale = 0.04419417382415922f; // 1/sqrt(512)
    float lmax = -INFINITY;
#pragma unroll 2
    for (int r = 0; r < 16; r++) {
        int t = wg + 1024 * r;
        const float4* kp = (const float4*)(enc + (size_t)t * 1024); // keys = first 512
        float s = 0.f;
#pragma unroll
        for (int i = 0; i < 4; i++) {
            int k = lane + 32 * i;
            float4 a = kp[k], h = sh4[k];
            s += a.x * h.x + a.y * h.y + a.z * h.z + a.w * h.w;
        }
#pragma unroll
        for (int o = 16; o > 0; o >>= 1) s += __shfl_xor_sync(~0u, s, o);
        if (lane == 0) {
            s *= scale;
            g_scores[t] = s;
            lmax = fmaxf(lmax, s);
        }
    }
    if (lane == 0) smax[wid] = lmax;
    __syncthreads();
    if (tid == 0) {
        float m = smax[0];
#pragma unroll
        for (int i = 1; i < 8; i++) m = fmaxf(m, smax[i]);
        g_blockmax[blockIdx.x] = m;
    }
}

// ---------------- exp + partial Z / partial U: 128 blocks x 256 threads ------
__global__ void k_attnsum(const float* __restrict__ enc, float* __restrict__ attn_out) {
    __shared__ float se[128];
    __shared__ float sred[128];
    int tid = threadIdx.x;

    // global max (deterministic tree reduce of 128 block maxes)
    if (tid < 128) sred[tid] = g_blockmax[tid];
    __syncthreads();
    for (int o = 64; o > 0; o >>= 1) {
        if (tid < o) sred[tid] = fmaxf(sred[tid], sred[tid + o]);
        __syncthreads();
    }
    float m = sred[0];
    __syncthreads();

    int t0 = blockIdx.x * 128;
    if (tid < 128) {
        float e = expf(g_scores[t0 + tid] - m);
        se[tid] = e;
        sred[tid] = e;
        if (attn_out) attn_out[t0 + tid] = e;   // unnormalized; divided by Z later
    }
    __syncthreads();
    for (int o = 64; o > 0; o >>= 1) {
        if (tid < o) sred[tid] += sred[tid + o];
        __syncthreads();
    }
    if (tid == 0) g_partZ[blockIdx.x] = sred[0];

    // partial U: thread handles value cols (2*tid, 2*tid+1)
    float2 acc = make_float2(0.f, 0.f);
    const float2* vp = (const float2*)enc;     // row t in float2: t*512, values at +256
#pragma unroll 4
    for (int i = 0; i < 128; i++) {
        float e = se[i];
        float2 v = vp[(size_t)(t0 + i) * 512 + 256 + tid];
        acc.x += e * v.x;
        acc.y += e * v.y;
    }
    g_partU[blockIdx.x * 512 + 2 * tid]     = acc.x;
    g_partU[blockIdx.x * 512 + 2 * tid + 1] = acc.y;
}

// ---------------- finalize: 1 block x 512 threads -----------------------------
__global__ void k_final(const float* __restrict__ embed, const float* __restrict__ w_out,
                        const float* __restrict__ b_out, float* __restrict__ out_logits,
                        int step) {
    __shared__ __align__(16) float scat[1024];
    __shared__ float slog[VOCAB + 1];
    __shared__ float sz[128];
    __shared__ int   sbest;
    int tid = threadIdx.x;

    // Z (deterministic)
    if (tid < 128) sz[tid] = g_partZ[tid];
    __syncthreads();
    for (int o = 64; o > 0; o >>= 1) {
        if (tid < o) sz[tid] += sz[tid + o];
        __syncthreads();
    }
    float Z = sz[0];

    // U reduce over 128 blocks (fixed order) -> summary = U/Z
    float u = 0.f;
#pragma unroll 8
    for (int b = 0; b < 128; b++) u += g_partU[b * 512 + tid];
    scat[tid] = u / Z;
    float hn = g_hnew[tid];
    scat[512 + tid] = hn;
    g_h[tid] = hn;                       // commit hidden state
    if (tid == 0) g_Z[step] = Z;
    __syncthreads();

    // logits: 16 warps, each handles rows wid and wid+16
    int wid = tid >> 5, lane = tid & 31;
#pragma unroll
    for (int rr = 0; rr < 2; rr++) {
        int row = wid + 16 * rr;
        if (row < VOCAB) {
            const float4* wp = (const float4*)(w_out + (size_t)row * 1024);
            float s = 0.f;
#pragma unroll
            for (int i = 0; i < 8; i++) {
                int k = lane + 32 * i;
                float4 a = wp[k];
                float4 c = ((const float4*)scat)[k];
                s += a.x * c.x + a.y * c.y + a.z * c.z + a.w * c.w;
            }
#pragma unroll
            for (int o = 16; o > 0; o >>= 1) s += __shfl_xor_sync(~0u, s, o);
            if (lane == 0) {
                s += b_out[row];
                if (out_logits) out_logits[row] = s;
                slog[row] = s;
            }
        }
    }
    __syncthreads();
    if (tid == 0) {
        float bv = slog[0]; int bi = 0;
        for (int v = 1; v < VOCAB; v++)
            if (slog[v] > bv) { bv = slog[v]; bi = v; }   // first-max tie-break (jnp.argmax)
        g_best[step] = bi;
        sbest = bi;
    }
    __syncthreads();
    g_y[tid] = embed[sbest * EMB + tid];   // feedback token embedding
}

// ---------------- normalize attentions by per-step Z --------------------------
__global__ void k_norm(float* __restrict__ attn) {
    int i = blockIdx.x * 256 + threadIdx.x;   // 100*16384 total
    attn[i] = attn[i] / g_Z[i >> 14];
}

// ---------------- length (first EOS) ------------------------------------------
__global__ void k_len(float* __restrict__ outp) {
    int len = MAX_LEN;
    for (int i = 0; i < MAX_LEN; i++)
        if (g_best[i] == EOS_IDX) { len = i; break; }
    *outp = (float)len;
}

// ------------------------------------------------------------------------------
extern "C" void kernel_launch(void* const* d_in, const int* in_sizes, int n_in,
                              void* d_out, int out_size) {
    const float* enc   = (const float*)d_in[0];
    // d_in[1] encoding_lens (int64) unused: always T_ENC
    const float* embed = (const float*)d_in[2];
    const float* w_ih  = (const float*)d_in[3];
    const float* w_hh  = (const float*)d_in[4];
    const float* b_ih  = (const float*)d_in[5];
    const float* b_hh  = (const float*)d_in[6];
    const float* w_out = (const float*)d_in[7];
    const float* b_out = (const float*)d_in[8];

    float* outF = (float*)d_out;
    const long long N_LOG  = (long long)MAX_LEN * VOCAB;        // 3100
    const long long N_ATTN = (long long)MAX_LEN * T_ENC;        // 1638400

    float* out_logits = outF;
    float* out_len    = nullptr;
    float* out_attn   = nullptr;
    if ((long long)out_size >= N_LOG + 1 + N_ATTN) {            // logits | len | attn
        out_len  = outF + N_LOG;
        out_attn = outF + N_LOG + 1;
    } else if ((long long)out_size >= N_LOG + N_ATTN) {         // logits | attn
        out_attn = outF + N_LOG;
    } else if ((long long)out_size == N_ATTN) {                 // attn only
        out_attn = outF;
        out_logits = nullptr;
    }                                                           // else: logits only

    k_init<<<1, 512>>>(embed);
    for (int step = 0; step < MAX_LEN; step++) {
        k_gru<<<64, 256>>>(w_ih, w_hh, b_ih, b_hh);
        k_scores<<<NB_B, 256>>>(enc);
        float* ao = out_attn ? out_attn + (size_t)step * T_ENC : nullptr;
        k_attnsum<<<NB_C, 256>>>(enc, ao);
        float* lo = out_logits ? out_logits + (size_t)step * VOCAB : nullptr;
        k_final<<<1, 512>>>(embed, w_out, b_out, lo, step);
    }
    if (out_attn) k_norm<<<(MAX_LEN * T_ENC) / 256, 256>>>(out_attn);
    if (out_len)  k_len<<<1, 1>>>(out_len);
}

// round 5
// speedup vs baseline: 1.7678x; 1.7678x over previous
#include <cuda_runtime.h>
#include <math.h>

#define HID     512
#define EMB     512
#define VOCAB   31
#define T_ENC   16384
#define MAX_LEN 100
#define EOS_IDX 29

#define NB_F   296                 // fused-kernel CTAs (2 per SM)
#define NWARP  (NB_F * 8)          // warps in fused kernel
#define NB_R   37                  // reduce CTAs (296/8)

// ---------------- device scratch ----------------------------------------------
__device__ float g_h[HID];
__device__ float g_y[EMB];
__device__ float g_hnew[HID];
__device__ float g_partU[NB_F * HID];
__device__ float g_partZ[NB_F];
__device__ float g_U2[NB_R * HID];
__device__ float g_Z2[NB_R];
__device__ float g_Z[MAX_LEN];
__device__ int   g_best[MAX_LEN];
__device__ float g_attn_scratch[T_ENC];   // fallback attn target

// ---------------- init ---------------------------------------------------------
__global__ void k_init(const float* __restrict__ embed) {
    int i = threadIdx.x;               // 512
    g_h[i] = 0.f;
    g_y[i] = embed[EOS_IDX * EMB + i];
}

// ---------------- GRU: 128 CTAs x 256 threads ----------------------------------
// CTA handles 4 outputs. Warps 0-3: w_ih dots (gates r,z,n) for output j;
// warps 4-7: w_hh dots. Combine in smem.
__global__ void k_gru(const float* __restrict__ w_ih, const float* __restrict__ w_hh,
                      const float* __restrict__ b_ih, const float* __restrict__ b_hh) {
    __shared__ __align__(16) float4 sx[EMB / 4];
    __shared__ __align__(16) float4 sh[HID / 4];
    __shared__ float sg[8][3];
    int tid = threadIdx.x;
    if (tid < 128)       sx[tid]       = ((const float4*)g_y)[tid];
    else if (tid < 256)  sh[tid - 128] = ((const float4*)g_h)[tid - 128];
    __syncthreads();

    int wid = tid >> 5, lane = tid & 31;
    int j = blockIdx.x * 4 + (wid & 3);
    bool is_hh = wid >= 4;
    const float*  W  = is_hh ? w_hh : w_ih;
    const float4* sv = is_hh ? sh : sx;

    const float4* wr = (const float4*)(W + (size_t)j * 512);
    const float4* wz = (const float4*)(W + (size_t)(512 + j) * 512);
    const float4* wn = (const float4*)(W + (size_t)(1024 + j) * 512);

    float gr = 0.f, gz = 0.f, gn = 0.f;
#pragma unroll
    for (int i = 0; i < 4; i++) {
        int k = lane + 32 * i;
        float4 x4 = sv[k], a;
        a = wr[k]; gr += a.x * x4.x + a.y * x4.y + a.z * x4.z + a.w * x4.w;
        a = wz[k]; gz += a.x * x4.x + a.y * x4.y + a.z * x4.z + a.w * x4.w;
        a = wn[k]; gn += a.x * x4.x + a.y * x4.y + a.z * x4.z + a.w * x4.w;
    }
#pragma unroll
    for (int o = 16; o > 0; o >>= 1) {
        gr += __shfl_xor_sync(~0u, gr, o);
        gz += __shfl_xor_sync(~0u, gz, o);
        gn += __shfl_xor_sync(~0u, gn, o);
    }
    if (lane == 0) { sg[wid][0] = gr; sg[wid][1] = gz; sg[wid][2] = gn; }
    __syncthreads();

    if (tid < 4) {
        int jj = blockIdx.x * 4 + tid;
        float ar = (sg[tid][0] + b_ih[jj])        + (sg[tid + 4][0] + b_hh[jj]);
        float az = (sg[tid][1] + b_ih[512 + jj])  + (sg[tid + 4][1] + b_hh[512 + jj]);
        float xn =  sg[tid][2] + b_ih[1024 + jj];
        float hn =  sg[tid + 4][2] + b_hh[1024 + jj];
        float r = 1.f / (1.f + expf(-ar));
        float z = 1.f / (1.f + expf(-az));
        float n = tanhf(xn + r * hn);
        g_hnew[jj] = (1.f - z) * n + z * ((const float*)g_h)[jj];
    }
}

// ---------------- fused scores+exp+Z+sum(e*v): 296 CTAs x 256 threads ----------
// Each warp streams full rows [key|value] (4KB each). No max subtraction
// (scores bounded: GRU hidden in (-1,1) elementwise => |s| <= sqrt(512) ~ 22.6).
__global__ void __launch_bounds__(256) k_fused(const float* __restrict__ enc,
                                               float* __restrict__ attn_out) {
    __shared__ __align__(16) float4 sh4[128];       // hnew
    __shared__ __align__(16) float  su[8][512];     // per-warp U partials
    __shared__ float sz[8];
    int tid = threadIdx.x;
    if (tid < 128) sh4[tid] = ((const float4*)g_hnew)[tid];
    __syncthreads();

    int wid = tid >> 5, lane = tid & 31;
    int gw = blockIdx.x * 8 + wid;
    const float scale = 0.04419417382415922f;       // 1/sqrt(512)

    float4 u0 = make_float4(0.f, 0.f, 0.f, 0.f);
    float4 u1 = u0, u2 = u0, u3 = u0;
    float zacc = 0.f;

    for (int t = gw; t < T_ENC; t += NWARP) {
        const float4* row = (const float4*)(enc + (size_t)t * 1024);
        // score: keys = first 128 float4s of the row
        float s = 0.f;
#pragma unroll
        for (int i = 0; i < 4; i++) {
            int k = lane + 32 * i;
            float4 a = row[k], h = sh4[k];
            s += a.x * h.x + a.y * h.y + a.z * h.z + a.w * h.w;
        }
#pragma unroll
        for (int o = 16; o > 0; o >>= 1) s += __shfl_xor_sync(~0u, s, o);
        float e = expf(s * scale);
        if (lane == 0) attn_out[t] = e;             // unnormalized; /Z later
        zacc += e;
        // weighted values: float4s 128..255 of the row
        {
            float4 v;
            v = row[128 + lane];  u0.x += e * v.x; u0.y += e * v.y; u0.z += e * v.z; u0.w += e * v.w;
            v = row[160 + lane];  u1.x += e * v.x; u1.y += e * v.y; u1.z += e * v.z; u1.w += e * v.w;
            v = row[192 + lane];  u2.x += e * v.x; u2.y += e * v.y; u2.z += e * v.z; u2.w += e * v.w;
            v = row[224 + lane];  u3.x += e * v.x; u3.y += e * v.y; u3.z += e * v.z; u3.w += e * v.w;
        }
    }

    // per-warp -> smem (col mapping: float4 chunk i, lane l -> cols 128*i + 4*l ..+3)
    ((float4*)&su[wid][4 * lane])[0]        = u0;
    ((float4*)&su[wid][128 + 4 * lane])[0]  = u1;
    ((float4*)&su[wid][256 + 4 * lane])[0]  = u2;
    ((float4*)&su[wid][384 + 4 * lane])[0]  = u3;
    if (lane == 0) sz[wid] = zacc;
    __syncthreads();

    // CTA reduce over 8 warps (fixed order)
#pragma unroll
    for (int rep = 0; rep < 2; rep++) {
        int c = tid + 256 * rep;
        float s = su[0][c];
#pragma unroll
        for (int w = 1; w < 8; w++) s += su[w][c];
        g_partU[blockIdx.x * 512 + c] = s;
    }
    if (tid == 0) {
        float s = sz[0];
#pragma unroll
        for (int w = 1; w < 8; w++) s += sz[w];
        g_partZ[blockIdx.x] = s;
    }
}

// ---------------- reduce 296 partials -> 37: 37 CTAs x 256 threads -------------
__global__ void k_reduce() {
    int g = blockIdx.x, tid = threadIdx.x;
#pragma unroll
    for (int rep = 0; rep < 2; rep++) {
        int c = tid + 256 * rep;
        float s = 0.f;
#pragma unroll
        for (int b = 0; b < 8; b++) s += g_partU[(g * 8 + b) * 512 + c];
        g_U2[g * 512 + c] = s;
    }
    if (tid == 0) {
        float s = 0.f;
#pragma unroll
        for (int b = 0; b < 8; b++) s += g_partZ[g * 8 + b];
        g_Z2[g] = s;
    }
}

// ---------------- finalize: 1 CTA x 1024 threads --------------------------------
__global__ void k_final(const float* __restrict__ embed, const float* __restrict__ w_out,
                        const float* __restrict__ b_out, float* __restrict__ out_logits,
                        int step) {
    __shared__ __align__(16) float scat[1024];
    __shared__ float slog[VOCAB + 1];
    __shared__ float sZ;
    __shared__ int   sbest;
    int tid = threadIdx.x;

    if (tid == 0) {
        float z = 0.f;
#pragma unroll
        for (int g = 0; g < NB_R; g++) z += g_Z2[g];
        sZ = z;
        g_Z[step] = z;
    }
    __syncthreads();
    float Z = sZ;

    if (tid < 512) {
        float u = 0.f;
#pragma unroll
        for (int g = 0; g < NB_R; g++) u += g_U2[g * 512 + tid];
        scat[tid] = u / Z;
        float hn = g_hnew[tid];
        scat[512 + tid] = hn;
        g_h[tid] = hn;                      // commit hidden state
    }
    __syncthreads();

    int wid = tid >> 5, lane = tid & 31;
    if (wid < VOCAB) {
        const float4* wp = (const float4*)(w_out + (size_t)wid * 1024);
        float s = 0.f;
#pragma unroll
        for (int i = 0; i < 8; i++) {
            int k = lane + 32 * i;
            float4 a = wp[k];
            float4 c = ((const float4*)scat)[k];
            s += a.x * c.x + a.y * c.y + a.z * c.z + a.w * c.w;
        }
#pragma unroll
        for (int o = 16; o > 0; o >>= 1) s += __shfl_xor_sync(~0u, s, o);
        if (lane == 0) {
            s += b_out[wid];
            if (out_logits) out_logits[wid] = s;
            slog[wid] = s;
        }
    }
    __syncthreads();
    if (tid == 0) {
        float bv = slog[0]; int bi = 0;
        for (int v = 1; v < VOCAB; v++)
            if (slog[v] > bv) { bv = slog[v]; bi = v; }   // first-max (jnp.argmax)
        g_best[step] = bi;
        sbest = bi;
    }
    __syncthreads();
    if (tid < 512) g_y[tid] = embed[sbest * EMB + tid];
}

// ---------------- normalize attentions by per-step Z ----------------------------
__global__ void k_norm(float* __restrict__ attn) {
    int i = blockIdx.x * 256 + threadIdx.x;
    attn[i] = attn[i] / g_Z[i >> 14];
}

// ---------------- length ---------------------------------------------------------
__global__ void k_len(float* __restrict__ outp) {
    int len = MAX_LEN;
    for (int i = 0; i < MAX_LEN; i++)
        if (g_best[i] == EOS_IDX) { len = i; break; }
    *outp = (float)len;
}

// ---------------------------------------------------------------------------------
extern "C" void kernel_launch(void* const* d_in, const int* in_sizes, int n_in,
                              void* d_out, int out_size) {
    const float* enc   = (const float*)d_in[0];
    const float* embed = (const float*)d_in[2];
    const float* w_ih  = (const float*)d_in[3];
    const float* w_hh  = (const float*)d_in[4];
    const float* b_ih  = (const float*)d_in[5];
    const float* b_hh  = (const float*)d_in[6];
    const float* w_out = (const float*)d_in[7];
    const float* b_out = (const float*)d_in[8];

    float* outF = (float*)d_out;
    const long long N_LOG  = (long long)MAX_LEN * VOCAB;        // 3100
    const long long N_ATTN = (long long)MAX_LEN * T_ENC;        // 1638400

    float* out_logits = outF;
    float* out_len    = nullptr;
    float* out_attn   = nullptr;
    if ((long long)out_size >= N_LOG + 1 + N_ATTN) {            // logits | len | attn
        out_len  = outF + N_LOG;
        out_attn = outF + N_LOG + 1;
    } else if ((long long)out_size >= N_LOG + N_ATTN) {
        out_attn = outF + N_LOG;
    } else if ((long long)out_size == N_ATTN) {
        out_attn = outF;
        out_logits = nullptr;
    }

    // fallback attn target if attentions are not part of the output
    float* attn_fallback = nullptr;
    cudaGetSymbolAddress((void**)&attn_fallback, g_attn_scratch);

    k_init<<<1, 512>>>(embed);
    for (int step = 0; step < MAX_LEN; step++) {
        k_gru<<<128, 256>>>(w_ih, w_hh, b_ih, b_hh);
        float* ao = out_attn ? out_attn + (size_t)step * T_ENC : attn_fallback;
        k_fused<<<NB_F, 256>>>(enc, ao);
        k_reduce<<<NB_R, 256>>>();
        float* lo = out_logits ? out_logits + (size_t)step * VOCAB : nullptr;
        k_final<<<1, 1024>>>(embed, w_out, b_out, lo, step);
    }
    if (out_attn) k_norm<<<(MAX_LEN * T_ENC) / 256, 256>>>(out_attn);
    if (out_len)  k_len<<<1, 1>>>(out_len);
}